// round 13
// baseline (speedup 1.0000x reference)
#include <cuda_runtime.h>
#include <math.h>

#define BB 8
#define QQ 1024
#define KN 1024
#define CC 16
#define OUTD 32
#define HH 16
#define WINDOW 0.25f
#define NTAB 1024
#define CHB 4            // channels per main-kernel block
#define QTHREADS 256
#define TBLK (NTAB / 256)   // 4 table blocks per channel

// -------- device scratch (no allocations allowed) --------
__device__ float2 g_tab2[CC][NTAB];          // duplicated pairs (t[i], t[i+1])
__device__ float  g_pos[BB][KN];             // keys sorted by channel
__device__ float  g_val[BB][KN];             // values[b,k,ch_k] sorted by channel
__device__ int    g_seg[BB][CC + 1];         // channel segment offsets
__device__ float  g_td[BB * QQ * 2 * CC];    // [targets(16) | dens(16)] per (b,q)

// ------------------------------------------------------------
// MLP eval reading weights from shared memory (no reg blowup)
// ------------------------------------------------------------
__device__ __forceinline__ float mlp_eval_smem(float a, int ch,
    const float* sW0, const float* sb0,
    const float* sW1, const float* sb1,
    const float* sW2, const float* sb2,
    const float* sW3, float sb3v) {
    float h0[HH], h1[HH];
#pragma unroll
    for (int j = 0; j < HH; j++) {
        float v = a * sW0[j * (CC + 1)] + sW0[j * (CC + 1) + 1 + ch] + sb0[j];
        h0[j] = v > 0.0f ? v : 0.0f;
    }
#pragma unroll
    for (int j = 0; j < HH; j++) {
        float sacc = sb1[j];
#pragma unroll
        for (int l = 0; l < HH; l++) sacc = fmaf(sW1[j * HH + l], h0[l], sacc);
        h1[j] = sacc > 0.0f ? sacc : 0.0f;
    }
#pragma unroll
    for (int j = 0; j < HH; j++) {
        float sacc = sb2[j];
#pragma unroll
        for (int l = 0; l < HH; l++) sacc = fmaf(sW2[j * HH + l], h1[l], sacc);
        h0[j] = sacc > 0.0f ? sacc : 0.0f;   // reuse as h2
    }
    float sacc = sb3v;
#pragma unroll
    for (int l = 0; l < HH; l++) sacc = fmaf(sW3[l], h0[l], sacc);
    return fabsf(sacc);
}

// ============================================================
// Kernel 1 (prep): blocks [0, TBLK*CC) tabulate the MLP as
// float2 pairs (weights staged in smem); blocks [TBLK*CC, +BB)
// counting-sort keys by channel.
// ============================================================
__global__ void __launch_bounds__(256)
prep_kernel(const float* __restrict__ keys_in,
            const float* __restrict__ values,
            const float* __restrict__ W0, const float* __restrict__ b0,
            const float* __restrict__ W1, const float* __restrict__ b1,
            const float* __restrict__ W2, const float* __restrict__ b2,
            const float* __restrict__ W3, const float* __restrict__ b3) {
    int bx  = blockIdx.x;
    int tid = threadIdx.x;

    if (bx < TBLK * CC) {
        // ---- table build ----
        __shared__ float sW0[HH * (CC + 1)];   // 272
        __shared__ float sb0[HH];
        __shared__ float sW1[HH * HH];         // 256
        __shared__ float sb1[HH];
        __shared__ float sW2[HH * HH];         // 256
        __shared__ float sb2[HH];
        __shared__ float sW3[HH];
        __shared__ float sb3;
        __shared__ float s[257];

        // cooperative weight staging
        for (int i = tid; i < HH * (CC + 1); i += 256) sW0[i] = W0[i];
        for (int i = tid; i < HH * HH; i += 256) { sW1[i] = W1[i]; sW2[i] = W2[i]; }
        if (tid < HH) { sb0[tid] = b0[tid]; sb1[tid] = b1[tid];
                        sb2[tid] = b2[tid]; sW3[tid] = W3[tid]; }
        if (tid == 0) sb3 = b3[0];
        __syncthreads();

        int ch   = bx / TBLK;
        int base = (bx % TBLK) * 256;
        const float STEP = WINDOW / (float)NTAB;

        s[tid] = mlp_eval_smem((float)(base + tid) * STEP, ch,
                               sW0, sb0, sW1, sb1, sW2, sb2, sW3, sb3);
        if (tid == 0)
            s[256] = mlp_eval_smem((float)(base + 256) * STEP, ch,
                                   sW0, sb0, sW1, sb1, sW2, sb2, sW3, sb3);
        __syncthreads();
        g_tab2[ch][base + tid] = make_float2(s[tid], s[tid + 1]);
    } else {
        // ---- counting sort by channel for batch b ----
        int b = bx - TBLK * CC;
        __shared__ int cnt[CC];
        __shared__ int cur[CC];
        if (tid < CC) cnt[tid] = 0;
        __syncthreads();
        for (int k = tid; k < KN; k += blockDim.x) {
            int ch = (int)keys_in[(b * KN + k) * 2];
            atomicAdd(&cnt[ch], 1);
        }
        __syncthreads();
        if (tid == 0) {
            int acc = 0;
            for (int c = 0; c < CC; c++) {
                g_seg[b][c] = acc;
                cur[c] = acc;
                acc += cnt[c];
            }
            g_seg[b][CC] = acc;
        }
        __syncthreads();
        for (int k = tid; k < KN; k += blockDim.x) {
            int   ch  = (int)keys_in[(b * KN + k) * 2];
            float pos = keys_in[(b * KN + k) * 2 + 1];
            int r = atomicAdd(&cur[ch], 1);
            g_pos[b][r] = pos;
            g_val[b][r] = values[(b * KN + k) * CC + ch];
        }
    }
}

// ============================================================
// Kernel 2: main pairwise accumulation via table lookup
// grid = (Q/256, 16/CHB, B), block = 256, thread = one query
// ============================================================
__global__ void main_kernel(const float* __restrict__ queries,
                            const float* __restrict__ Wd,
                            const float* __restrict__ bd) {
    extern __shared__ float2 sm[];
    float2* stab = sm;                 // CHB * NTAB duplicated pairs
    float2* skey = sm + CHB * NTAB;    // (pos, val) for this channel chunk

    int tid = threadIdx.x;
    int b   = blockIdx.z;
    int c0  = blockIdx.y * CHB;
    int q0  = blockIdx.x * QTHREADS;

    int soff[CHB + 1];
#pragma unroll
    for (int i = 0; i <= CHB; i++) soff[i] = g_seg[b][c0 + i];
    int s0  = soff[0];
    int len = soff[CHB] - s0;

    // stage table chunk into smem (one 8B load per entry)
#pragma unroll
    for (int cl = 0; cl < CHB; cl++) {
        const float2* tb = g_tab2[c0 + cl];
        for (int i = tid; i < NTAB; i += QTHREADS)
            stab[cl * NTAB + i] = tb[i];
    }
    // stage keys of this chunk
    for (int k = tid; k < len; k += QTHREADS)
        skey[k] = make_float2(g_pos[b][s0 + k], g_val[b][s0 + k]);
    __syncthreads();

    float qv  = queries[b * QQ + q0 + tid];
    float wdv = Wd[0];
    float bdv = bd[0];
    const float SCALE = (float)NTAB / WINDOW;
    int qi = (b * QQ + q0 + tid) * (2 * CC);

#pragma unroll
    for (int cl = 0; cl < CHB; cl++) {
        int kb = soff[cl] - s0;
        int ke = soff[cl + 1] - s0;
        const float2* tb = stab + cl * NTAB;
        float den = 0.0f, num = 0.0f;
#pragma unroll 4
        for (int k = kb; k < ke; k++) {
            float2 kv = skey[k];                 // warp-uniform broadcast LDS
            float ad = fabsf(kv.x - qv);         // identical to ref's |pos - q|
            if (ad < WINDOW) {                   // identical strict mask
                float t  = ad * SCALE;
                int   i  = (int)t;
                float fr = t - (float)i;
                float2 tt = tb[i];               // one LDS.64
                float w = fmaf(tt.y - tt.x, fr, tt.x);
                den += w;
                num = fmaf(w, kv.y, num);
            }
        }
        float target = num / (den + 1e-5f);
        float x  = (den * 0.1f - 1.0f) * wdv + bdv;
        float dn = 1.0f / (1.0f + expf(-x));
        g_td[qi + c0 + cl]      = target;
        g_td[qi + CC + c0 + cl] = dn;
    }
}

// ============================================================
// Kernel 3: epilogue  out = [targets | dens] @ Wr^T + br
// block = 256 threads = 8 queries x 32 outputs; grid = B*Q/8
// ============================================================
__global__ void epilogue_kernel(const float* __restrict__ Wr,
                                const float* __restrict__ br,
                                float* __restrict__ out) {
    __shared__ float sWrT[2 * CC][OUTD];   // transposed: sWrT[i][o] = Wr[o][i]
    __shared__ float sbr[OUTD];
    __shared__ float scat[8][2 * CC];
    int tid = threadIdx.x;

    // stage ALL of Wr transposed: 1024 elements, 256 threads -> 4 each
#pragma unroll
    for (int e = tid; e < OUTD * 2 * CC; e += 256) {
        int o = e / (2 * CC);
        int i = e % (2 * CC);
        sWrT[i][o] = Wr[e];
    }
    if (tid < OUTD) sbr[tid] = br[tid];

    int q0 = blockIdx.x * 8;               // flat (b,q) base
    // stage 8 query cat rows, coalesced (256 floats)
    scat[tid >> 5][tid & 31] = g_td[q0 * (2 * CC) + tid];
    __syncthreads();

    int ql = tid >> 5;                     // warp = one query
    int o  = tid & 31;                     // lane = one output
    float acc = sbr[o];
#pragma unroll
    for (int i = 0; i < 2 * CC; i++)
        acc = fmaf(sWrT[i][o], scat[ql][i], acc);   // conflict-free + broadcast
    out[(q0 + ql) * OUTD + o] = acc;
}

// ============================================================
extern "C" void kernel_launch(void* const* d_in, const int* in_sizes, int n_in,
                              void* d_out, int out_size) {
    const float* keys_in = (const float*)d_in[0];
    const float* queries = (const float*)d_in[1];
    const float* values  = (const float*)d_in[2];
    const float* W0 = (const float*)d_in[3];
    const float* b0 = (const float*)d_in[4];
    const float* W1 = (const float*)d_in[5];
    const float* b1 = (const float*)d_in[6];
    const float* W2 = (const float*)d_in[7];
    const float* b2 = (const float*)d_in[8];
    const float* W3 = (const float*)d_in[9];
    const float* b3 = (const float*)d_in[10];
    const float* Wd = (const float*)d_in[11];
    const float* bd = (const float*)d_in[12];
    const float* Wr = (const float*)d_in[13];
    const float* br = (const float*)d_in[14];
    float* out = (float*)d_out;

    const size_t main_smem = (size_t)(CHB * NTAB) * sizeof(float2)
                           + (size_t)KN * sizeof(float2);
    cudaFuncSetAttribute(main_kernel, cudaFuncAttributeMaxDynamicSharedMemorySize,
                         (int)main_smem);

    prep_kernel<<<TBLK * CC + BB, 256>>>(keys_in, values,
                                         W0, b0, W1, b1, W2, b2, W3, b3);

    dim3 mgrid(QQ / QTHREADS, CC / CHB, BB);
    main_kernel<<<mgrid, QTHREADS, main_smem>>>(queries, Wd, bd);

    epilogue_kernel<<<BB * QQ / 8, 256>>>(Wr, br, out);
}

// round 15
// speedup vs baseline: 2.0227x; 2.0227x over previous
#include <cuda_runtime.h>
#include <math.h>

#define BB 8
#define QQ 1024
#define KN 1024
#define CC 16
#define OUTD 32
#define HH 16
#define WINDOW 0.25f
#define NTAB 1024
#define CHB 4               // channels per main-kernel block
#define QTHREADS 256
#define PTHREADS 128        // prep block size
#define TBLK (NTAB / PTHREADS)   // 8 table blocks per channel

// -------- device scratch (no allocations allowed) --------
__device__ float2 g_tab2[CC][NTAB];          // duplicated pairs (t[i], t[i+1])
__device__ float  g_pos[BB][KN];             // keys sorted by channel
__device__ float  g_val[BB][KN];             // values[b,k,ch_k] sorted by channel
__device__ int    g_seg[BB][CC + 1];         // channel segment offsets
__device__ float  g_td[BB * QQ * 2 * CC];    // [targets(16) | dens(16)] per (b,q)

// ------------------------------------------------------------
// Streaming MLP eval: layer-0 activations are consumed as they
// are produced (fan-out into 16 independent accumulators), so
// peak register liveness stays low and ILP stays high.
// ------------------------------------------------------------
__device__ __forceinline__ float mlp_eval_stream(float a, int ch,
    const float* sW0, const float* sb0,
    const float* sW1, const float* sb1,
    const float* sW2, const float* sb2,
    const float* sW3, float sb3v) {
    float acc1[HH], acc2[HH];
#pragma unroll
    for (int j = 0; j < HH; j++) acc1[j] = sb1[j];
#pragma unroll
    for (int l = 0; l < HH; l++) {
        float v = fmaf(a, sW0[l * (CC + 1)], sW0[l * (CC + 1) + 1 + ch] + sb0[l]);
        v = v > 0.0f ? v : 0.0f;
#pragma unroll
        for (int j = 0; j < HH; j++) acc1[j] = fmaf(sW1[j * HH + l], v, acc1[j]);
    }
#pragma unroll
    for (int j = 0; j < HH; j++) acc2[j] = sb2[j];
#pragma unroll
    for (int l = 0; l < HH; l++) {
        float v = acc1[l] > 0.0f ? acc1[l] : 0.0f;
#pragma unroll
        for (int j = 0; j < HH; j++) acc2[j] = fmaf(sW2[j * HH + l], v, acc2[j]);
    }
    float o = sb3v;
#pragma unroll
    for (int l = 0; l < HH; l++) {
        float v = acc2[l] > 0.0f ? acc2[l] : 0.0f;
        o = fmaf(sW3[l], v, o);
    }
    return fabsf(o);
}

// ============================================================
// Kernel 1 (prep): blocks [0, TBLK*CC) tabulate the MLP as
// float2 pairs; blocks [TBLK*CC, +BB) counting-sort keys.
// __launch_bounds__(128, 1): min-blocks hint keeps ptxas from
// starving registers (round-13 regression: 32 regs -> local mem).
// ============================================================
__global__ void __launch_bounds__(PTHREADS, 1)
prep_kernel(const float* __restrict__ keys_in,
            const float* __restrict__ values,
            const float* __restrict__ W0, const float* __restrict__ b0,
            const float* __restrict__ W1, const float* __restrict__ b1,
            const float* __restrict__ W2, const float* __restrict__ b2,
            const float* __restrict__ W3, const float* __restrict__ b3) {
    int bx  = blockIdx.x;
    int tid = threadIdx.x;

    if (bx < TBLK * CC) {
        // ---- table build ----
        __shared__ float sW0[HH * (CC + 1)];
        __shared__ float sb0[HH];
        __shared__ float sW1[HH * HH];
        __shared__ float sb1[HH];
        __shared__ float sW2[HH * HH];
        __shared__ float sb2[HH];
        __shared__ float sW3[HH];
        __shared__ float sb3;
        __shared__ float s[PTHREADS + 1];

        for (int i = tid; i < HH * (CC + 1); i += PTHREADS) sW0[i] = W0[i];
        for (int i = tid; i < HH * HH; i += PTHREADS) { sW1[i] = W1[i]; sW2[i] = W2[i]; }
        if (tid < HH) { sb0[tid] = b0[tid]; sb1[tid] = b1[tid];
                        sb2[tid] = b2[tid]; sW3[tid] = W3[tid]; }
        if (tid == 0) sb3 = b3[0];
        __syncthreads();

        int ch   = bx / TBLK;
        int base = (bx % TBLK) * PTHREADS;
        const float STEP = WINDOW / (float)NTAB;

        s[tid] = mlp_eval_stream((float)(base + tid) * STEP, ch,
                                 sW0, sb0, sW1, sb1, sW2, sb2, sW3, sb3);
        if (tid == 0)
            s[PTHREADS] = mlp_eval_stream((float)(base + PTHREADS) * STEP, ch,
                                          sW0, sb0, sW1, sb1, sW2, sb2, sW3, sb3);
        __syncthreads();
        g_tab2[ch][base + tid] = make_float2(s[tid], s[tid + 1]);
    } else {
        // ---- counting sort by channel for batch b ----
        int b = bx - TBLK * CC;
        __shared__ int cnt[CC];
        __shared__ int cur[CC];
        if (tid < CC) cnt[tid] = 0;
        __syncthreads();
        for (int k = tid; k < KN; k += PTHREADS) {
            int ch = (int)keys_in[(b * KN + k) * 2];
            atomicAdd(&cnt[ch], 1);
        }
        __syncthreads();
        if (tid == 0) {
            int acc = 0;
            for (int c = 0; c < CC; c++) {
                g_seg[b][c] = acc;
                cur[c] = acc;
                acc += cnt[c];
            }
            g_seg[b][CC] = acc;
        }
        __syncthreads();
        for (int k = tid; k < KN; k += PTHREADS) {
            int   ch  = (int)keys_in[(b * KN + k) * 2];
            float pos = keys_in[(b * KN + k) * 2 + 1];
            int r = atomicAdd(&cur[ch], 1);
            g_pos[b][r] = pos;
            g_val[b][r] = values[(b * KN + k) * CC + ch];
        }
    }
}

// ============================================================
// Kernel 2: main pairwise accumulation via table lookup
// grid = (Q/256, 16/CHB, B), block = 256, thread = one query
// ============================================================
__global__ void main_kernel(const float* __restrict__ queries,
                            const float* __restrict__ Wd,
                            const float* __restrict__ bd) {
    extern __shared__ float2 sm[];
    float2* stab = sm;                 // CHB * NTAB duplicated pairs
    float2* skey = sm + CHB * NTAB;    // (pos, val) for this channel chunk

    int tid = threadIdx.x;
    int b   = blockIdx.z;
    int c0  = blockIdx.y * CHB;
    int q0  = blockIdx.x * QTHREADS;

    int soff[CHB + 1];
#pragma unroll
    for (int i = 0; i <= CHB; i++) soff[i] = g_seg[b][c0 + i];
    int s0  = soff[0];
    int len = soff[CHB] - s0;

    // stage table chunk into smem (one 8B load per entry)
#pragma unroll
    for (int cl = 0; cl < CHB; cl++) {
        const float2* tb = g_tab2[c0 + cl];
        for (int i = tid; i < NTAB; i += QTHREADS)
            stab[cl * NTAB + i] = tb[i];
    }
    // stage keys of this chunk
    for (int k = tid; k < len; k += QTHREADS)
        skey[k] = make_float2(g_pos[b][s0 + k], g_val[b][s0 + k]);
    __syncthreads();

    float qv  = queries[b * QQ + q0 + tid];
    float wdv = Wd[0];
    float bdv = bd[0];
    const float SCALE = (float)NTAB / WINDOW;
    int qi = (b * QQ + q0 + tid) * (2 * CC);

#pragma unroll
    for (int cl = 0; cl < CHB; cl++) {
        int kb = soff[cl] - s0;
        int ke = soff[cl + 1] - s0;
        const float2* tb = stab + cl * NTAB;
        float den = 0.0f, num = 0.0f;
#pragma unroll 4
        for (int k = kb; k < ke; k++) {
            float2 kv = skey[k];                 // warp-uniform broadcast LDS
            float ad = fabsf(kv.x - qv);         // identical to ref's |pos - q|
            if (ad < WINDOW) {                   // identical strict mask
                float t  = ad * SCALE;
                int   i  = (int)t;
                float fr = t - (float)i;
                float2 tt = tb[i];               // one LDS.64
                float w = fmaf(tt.y - tt.x, fr, tt.x);
                den += w;
                num = fmaf(w, kv.y, num);
            }
        }
        float target = num / (den + 1e-5f);
        float x  = (den * 0.1f - 1.0f) * wdv + bdv;
        float dn = 1.0f / (1.0f + expf(-x));
        g_td[qi + c0 + cl]      = target;
        g_td[qi + CC + c0 + cl] = dn;
    }
}

// ============================================================
// Kernel 3: epilogue  out = [targets | dens] @ Wr^T + br
// block = 256 threads = 8 queries x 32 outputs; grid = B*Q/8
// ============================================================
__global__ void epilogue_kernel(const float* __restrict__ Wr,
                                const float* __restrict__ br,
                                float* __restrict__ out) {
    __shared__ float sWrT[2 * CC][OUTD];   // transposed: sWrT[i][o] = Wr[o][i]
    __shared__ float sbr[OUTD];
    __shared__ float scat[8][2 * CC];
    int tid = threadIdx.x;

    // stage ALL of Wr transposed: 1024 elements, 256 threads -> 4 each
#pragma unroll
    for (int e = tid; e < OUTD * 2 * CC; e += 256) {
        int o = e / (2 * CC);
        int i = e % (2 * CC);
        sWrT[i][o] = Wr[e];
    }
    if (tid < OUTD) sbr[tid] = br[tid];

    int q0 = blockIdx.x * 8;               // flat (b,q) base
    // stage 8 query cat rows, coalesced (256 floats)
    scat[tid >> 5][tid & 31] = g_td[q0 * (2 * CC) + tid];
    __syncthreads();

    int ql = tid >> 5;                     // warp = one query
    int o  = tid & 31;                     // lane = one output
    float acc = sbr[o];
#pragma unroll
    for (int i = 0; i < 2 * CC; i++)
        acc = fmaf(sWrT[i][o], scat[ql][i], acc);   // conflict-free + broadcast
    out[(q0 + ql) * OUTD + o] = acc;
}

// ============================================================
extern "C" void kernel_launch(void* const* d_in, const int* in_sizes, int n_in,
                              void* d_out, int out_size) {
    const float* keys_in = (const float*)d_in[0];
    const float* queries = (const float*)d_in[1];
    const float* values  = (const float*)d_in[2];
    const float* W0 = (const float*)d_in[3];
    const float* b0 = (const float*)d_in[4];
    const float* W1 = (const float*)d_in[5];
    const float* b1 = (const float*)d_in[6];
    const float* W2 = (const float*)d_in[7];
    const float* b2 = (const float*)d_in[8];
    const float* W3 = (const float*)d_in[9];
    const float* b3 = (const float*)d_in[10];
    const float* Wd = (const float*)d_in[11];
    const float* bd = (const float*)d_in[12];
    const float* Wr = (const float*)d_in[13];
    const float* br = (const float*)d_in[14];
    float* out = (float*)d_out;

    const size_t main_smem = (size_t)(CHB * NTAB) * sizeof(float2)
                           + (size_t)KN * sizeof(float2);
    cudaFuncSetAttribute(main_kernel, cudaFuncAttributeMaxDynamicSharedMemorySize,
                         (int)main_smem);

    prep_kernel<<<TBLK * CC + BB, PTHREADS>>>(keys_in, values,
                                              W0, b0, W1, b1, W2, b2, W3, b3);

    dim3 mgrid(QQ / QTHREADS, CC / CHB, BB);
    main_kernel<<<mgrid, QTHREADS, main_smem>>>(queries, Wd, bd);

    epilogue_kernel<<<BB * QQ / 8, 256>>>(Wr, br, out);
}

// round 16
// speedup vs baseline: 2.3670x; 1.1702x over previous
#include <cuda_runtime.h>
#include <math.h>

#define BB 8
#define QQ 1024
#define KN 1024
#define CC 16
#define OUTD 32
#define HH 16
#define WINDOW 0.25f
#define NTAB 1024
#define CHB 4               // channels per main-kernel block
#define QTHREADS 128
#define TBPC 65             // table blocks per channel (65*16=1040 >= NTAB+1)

// -------- device scratch (no allocations allowed) --------
__device__ float g_tab1[CC * (NTAB + 1)];    // scalar table samples
__device__ float g_pos[BB][KN];              // keys sorted by channel
__device__ float g_val[BB][KN];              // values[b,k,ch_k] sorted by channel
__device__ int   g_seg[BB][CC + 1];          // channel segment offsets
__device__ float g_td[BB * QQ * 2 * CC];     // [targets(16) | dens(16)] per (b,q)

// ============================================================
// Kernel 1 (prep):
//  blocks [0, CC*TBPC): shuffle-parallel MLP tabulation.
//    16 lanes cooperate per sample: lane j owns neuron j of each
//    hidden layer; activations exchanged with width-16 shuffles.
//    266K threads total (vs 16K) -> latency actually hidden.
//  blocks [CC*TBPC, +BB): counting-sort keys by channel.
// ============================================================
__global__ void prep_kernel(const float* __restrict__ keys_in,
                            const float* __restrict__ values,
                            const float* __restrict__ W0, const float* __restrict__ b0,
                            const float* __restrict__ W1, const float* __restrict__ b1,
                            const float* __restrict__ W2, const float* __restrict__ b2,
                            const float* __restrict__ W3, const float* __restrict__ b3) {
    int bx  = blockIdx.x;
    int tid = threadIdx.x;

    if (bx < CC * TBPC) {
        int ch = bx / TBPC;
        int bc = bx % TBPC;
        int g  = tid >> 4;          // sample group within block (0..15)
        int j  = tid & 15;          // neuron lane (0..15)
        int i  = bc * 16 + g;       // sample index (0..1039)
        const float STEP = WINDOW / (float)NTAB;
        float a = (float)i * STEP;

        // layer 0: h0_j = relu(a*W0[j,0] + W0[j,1+ch] + b0[j])
        float h = fmaf(a, __ldg(&W0[j * (CC + 1)]),
                       __ldg(&W0[j * (CC + 1) + 1 + ch]) + __ldg(&b0[j]));
        h = fmaxf(h, 0.0f);

        // layer 1: acc_j = b1[j] + sum_l W1[j,l] * h0_l  (same fmaf order)
        float acc = __ldg(&b1[j]);
#pragma unroll
        for (int l = 0; l < HH; l++)
            acc = fmaf(__ldg(&W1[j * HH + l]),
                       __shfl_sync(0xffffffffu, h, l, 16), acc);
        float h1 = fmaxf(acc, 0.0f);

        // layer 2
        acc = __ldg(&b2[j]);
#pragma unroll
        for (int l = 0; l < HH; l++)
            acc = fmaf(__ldg(&W2[j * HH + l]),
                       __shfl_sync(0xffffffffu, h1, l, 16), acc);
        float h2 = fmaxf(acc, 0.0f);

        // output: sum_j W3[j]*h2_j across the 16-lane group
        float o = __ldg(&W3[j]) * h2;
#pragma unroll
        for (int off = 8; off >= 1; off >>= 1)
            o += __shfl_xor_sync(0xffffffffu, o, off, 16);

        if (j == 0 && i <= NTAB)
            g_tab1[ch * (NTAB + 1) + i] = fabsf(o + __ldg(&b3[0]));
    } else {
        // ---- counting sort by channel for batch b ----
        int b = bx - CC * TBPC;
        __shared__ int cnt[CC];
        __shared__ int cur[CC];
        if (tid < CC) cnt[tid] = 0;
        __syncthreads();
        for (int k = tid; k < KN; k += blockDim.x) {
            int ch = (int)keys_in[(b * KN + k) * 2];
            atomicAdd(&cnt[ch], 1);
        }
        __syncthreads();
        if (tid == 0) {
            int acc = 0;
            for (int c = 0; c < CC; c++) {
                g_seg[b][c] = acc;
                cur[c] = acc;
                acc += cnt[c];
            }
            g_seg[b][CC] = acc;
        }
        __syncthreads();
        for (int k = tid; k < KN; k += blockDim.x) {
            int   ch  = (int)keys_in[(b * KN + k) * 2];
            float pos = keys_in[(b * KN + k) * 2 + 1];
            int r = atomicAdd(&cur[ch], 1);
            g_pos[b][r] = pos;
            g_val[b][r] = values[(b * KN + k) * CC + ch];
        }
    }
}

// ============================================================
// Kernel 2: main pairwise accumulation via table lookup.
// grid = (Q/128, 16/CHB, B), block = 128, thread = one query.
// Inner loop is branch-free: clamped table read + SEL mask.
// ============================================================
__global__ void main_kernel(const float* __restrict__ queries,
                            const float* __restrict__ Wd,
                            const float* __restrict__ bd) {
    extern __shared__ float2 sm[];
    float2* stab = sm;                 // CHB * NTAB pairs (t[i], t[i+1])
    float2* skey = sm + CHB * NTAB;    // (pos, val) for this channel chunk

    int tid = threadIdx.x;
    int b   = blockIdx.z;
    int c0  = blockIdx.y * CHB;
    int q0  = blockIdx.x * QTHREADS;

    int soff[CHB + 1];
#pragma unroll
    for (int i = 0; i <= CHB; i++) soff[i] = g_seg[b][c0 + i];
    int s0  = soff[0];
    int len = soff[CHB] - s0;

    // stage table chunk: pairs from scalar table (coalesced reads)
#pragma unroll
    for (int cl = 0; cl < CHB; cl++) {
        const float* t1 = g_tab1 + (c0 + cl) * (NTAB + 1);
        for (int i = tid; i < NTAB; i += QTHREADS)
            stab[cl * NTAB + i] = make_float2(t1[i], t1[i + 1]);
    }
    // stage keys of this chunk
    for (int k = tid; k < len; k += QTHREADS)
        skey[k] = make_float2(g_pos[b][s0 + k], g_val[b][s0 + k]);
    __syncthreads();

    float qv  = queries[b * QQ + q0 + tid];
    float wdv = Wd[0];
    float bdv = bd[0];
    const float SCALE = (float)NTAB / WINDOW;
    int qi = (b * QQ + q0 + tid) * (2 * CC);

#pragma unroll
    for (int cl = 0; cl < CHB; cl++) {
        int kb = soff[cl] - s0;
        int ke = soff[cl + 1] - s0;
        const float2* tb = stab + cl * NTAB;
        float den = 0.0f, num = 0.0f;
#pragma unroll 4
        for (int k = kb; k < ke; k++) {
            float2 kv = skey[k];                 // warp-uniform broadcast LDS
            float ad = fabsf(kv.x - qv);         // identical to ref's |pos - q|
            float t  = ad * SCALE;
            int   i  = (int)t;
            i = i < (NTAB - 1) ? i : (NTAB - 1); // clamp (also edge-safe)
            float fr = t - (float)i;
            float2 tt = tb[i];                   // unconditional LDS.64
            float w = fmaf(tt.y - tt.x, fr, tt.x);
            w = (ad < WINDOW) ? w : 0.0f;        // SEL, no branch
            den += w;
            num = fmaf(w, kv.y, num);
        }
        float target = num / (den + 1e-5f);
        float x  = (den * 0.1f - 1.0f) * wdv + bdv;
        float dn = 1.0f / (1.0f + expf(-x));
        g_td[qi + c0 + cl]      = target;
        g_td[qi + CC + c0 + cl] = dn;
    }
}

// ============================================================
// Kernel 3: epilogue  out = [targets | dens] @ Wr^T + br
// block = 256 threads = 8 queries x 32 outputs; grid = B*Q/8
// ============================================================
__global__ void epilogue_kernel(const float* __restrict__ Wr,
                                const float* __restrict__ br,
                                float* __restrict__ out) {
    __shared__ float sWrT[2 * CC][OUTD];   // transposed: sWrT[i][o] = Wr[o][i]
    __shared__ float sbr[OUTD];
    __shared__ float scat[8][2 * CC];
    int tid = threadIdx.x;

    // stage ALL of Wr transposed: 1024 elements, 256 threads -> 4 each
#pragma unroll
    for (int e = tid; e < OUTD * 2 * CC; e += 256) {
        int o = e / (2 * CC);
        int i = e % (2 * CC);
        sWrT[i][o] = Wr[e];
    }
    if (tid < OUTD) sbr[tid] = br[tid];

    int q0 = blockIdx.x * 8;               // flat (b,q) base
    scat[tid >> 5][tid & 31] = g_td[q0 * (2 * CC) + tid];
    __syncthreads();

    int ql = tid >> 5;                     // warp = one query
    int o  = tid & 31;                     // lane = one output
    float acc = sbr[o];
#pragma unroll
    for (int i = 0; i < 2 * CC; i++)
        acc = fmaf(sWrT[i][o], scat[ql][i], acc);   // conflict-free + broadcast
    out[(q0 + ql) * OUTD + o] = acc;
}

// ============================================================
extern "C" void kernel_launch(void* const* d_in, const int* in_sizes, int n_in,
                              void* d_out, int out_size) {
    const float* keys_in = (const float*)d_in[0];
    const float* queries = (const float*)d_in[1];
    const float* values  = (const float*)d_in[2];
    const float* W0 = (const float*)d_in[3];
    const float* b0 = (const float*)d_in[4];
    const float* W1 = (const float*)d_in[5];
    const float* b1 = (const float*)d_in[6];
    const float* W2 = (const float*)d_in[7];
    const float* b2 = (const float*)d_in[8];
    const float* W3 = (const float*)d_in[9];
    const float* b3 = (const float*)d_in[10];
    const float* Wd = (const float*)d_in[11];
    const float* bd = (const float*)d_in[12];
    const float* Wr = (const float*)d_in[13];
    const float* br = (const float*)d_in[14];
    float* out = (float*)d_out;

    const size_t main_smem = (size_t)(CHB * NTAB) * sizeof(float2)
                           + (size_t)KN * sizeof(float2);
    cudaFuncSetAttribute(main_kernel, cudaFuncAttributeMaxDynamicSharedMemorySize,
                         (int)main_smem);

    prep_kernel<<<CC * TBPC + BB, 256>>>(keys_in, values,
                                         W0, b0, W1, b1, W2, b2, W3, b3);

    dim3 mgrid(QQ / QTHREADS, CC / CHB, BB);
    main_kernel<<<mgrid, QTHREADS, main_smem>>>(queries, Wd, bd);

    epilogue_kernel<<<BB * QQ / 8, 256>>>(Wr, br, out);
}

// round 17
// speedup vs baseline: 2.8409x; 1.2002x over previous
#include <cuda_runtime.h>
#include <math.h>

#define BB 8
#define QQ 1024
#define KN 1024
#define CC 16
#define OUTD 32
#define HH 16
#define WINDOW 0.25f
#define NTAB 1024
#define CHB 4               // channels per main-kernel block
#define QTHREADS 128
#define TBPC 65             // table blocks per channel (65*16=1040 >= NTAB+1)

// -------- device scratch (no allocations allowed) --------
__device__ float g_tab1[CC * (NTAB + 1)];    // scalar table samples
__device__ float g_pos[BB][KN];              // keys sorted by channel
__device__ float g_val[BB][KN];              // values[b,k,ch_k] sorted by channel
__device__ int   g_seg[BB][CC + 1];          // channel segment offsets
__device__ float g_td[BB * QQ * 2 * CC];     // [targets(16) | dens(16)] per (b,q)

// ============================================================
// Kernel 1 (prep):
//  blocks [0, CC*TBPC): MLP tabulation, smem-mediated neuron
//    parallelism. Block = 16 samples x 16 neurons. Weights in
//    smem (padded rows -> conflict-free); activations passed
//    between layers via padded smem + syncthreads. No shuffles
//    on the critical path except the final 16-lane reduction.
//  blocks [CC*TBPC, +BB): counting-sort keys by channel.
// ============================================================
__global__ void __launch_bounds__(256)
prep_kernel(const float* __restrict__ keys_in,
            const float* __restrict__ values,
            const float* __restrict__ W0, const float* __restrict__ b0,
            const float* __restrict__ W1, const float* __restrict__ b1,
            const float* __restrict__ W2, const float* __restrict__ b2,
            const float* __restrict__ W3, const float* __restrict__ b3) {
    int bx  = blockIdx.x;
    int tid = threadIdx.x;

    if (bx < CC * TBPC) {
        __shared__ float sW1[HH * 17];     // row-padded: bank-conflict-free
        __shared__ float sW2[HH * 17];
        __shared__ float sW0a[HH];         // W0[j,0]
        __shared__ float sW0b[HH];         // W0[j,1+ch] + b0[j]
        __shared__ float sb1[HH];
        __shared__ float sb2[HH];
        __shared__ float sW3[HH];
        __shared__ float sb3v;
        __shared__ float sh[16][17];       // activations: sample x neuron (padded)

        int ch = bx / TBPC;
        int bc = bx % TBPC;

        // stage weights (padded rows)
        for (int e = tid; e < HH * HH; e += 256) {
            int r = e >> 4, c = e & 15;
            sW1[r * 17 + c] = W1[e];
            sW2[r * 17 + c] = W2[e];
        }
        if (tid < HH) {
            sW0a[tid] = W0[tid * (CC + 1)];
            sW0b[tid] = W0[tid * (CC + 1) + 1 + ch] + b0[tid];
            sb1[tid]  = b1[tid];
            sb2[tid]  = b2[tid];
            sW3[tid]  = W3[tid];
        }
        if (tid == 0) sb3v = b3[0];
        __syncthreads();

        int s = tid >> 4;                  // sample slot in block (0..15)
        int j = tid & 15;                  // neuron lane (0..15)
        int i = bc * 16 + s;               // global sample index
        const float STEP = WINDOW / (float)NTAB;
        float a = (float)i * STEP;

        // layer 0
        float h = fmaf(a, sW0a[j], sW0b[j]);
        h = fmaxf(h, 0.0f);
        sh[s][j] = h;
        __syncthreads();

        // layer 1: acc_j = b1[j] + sum_l W1[j,l] * h0_l
        float acc = sb1[j];
#pragma unroll
        for (int l = 0; l < HH; l++)
            acc = fmaf(sW1[j * 17 + l], sh[s][l], acc);
        acc = fmaxf(acc, 0.0f);
        __syncthreads();                   // all reads done before overwrite
        sh[s][j] = acc;
        __syncthreads();

        // layer 2
        acc = sb2[j];
#pragma unroll
        for (int l = 0; l < HH; l++)
            acc = fmaf(sW2[j * 17 + l], sh[s][l], acc);
        acc = fmaxf(acc, 0.0f);

        // output: reduce W3[j]*h2_j over the 16 neuron lanes
        float o = sW3[j] * acc;
#pragma unroll
        for (int off = 8; off >= 1; off >>= 1)
            o += __shfl_xor_sync(0xffffffffu, o, off, 16);

        if (j == 0 && i <= NTAB)
            g_tab1[ch * (NTAB + 1) + i] = fabsf(o + sb3v);
    } else {
        // ---- counting sort by channel for batch b ----
        int b = bx - CC * TBPC;
        __shared__ int cnt[CC];
        __shared__ int cur[CC];
        if (tid < CC) cnt[tid] = 0;
        __syncthreads();
        for (int k = tid; k < KN; k += blockDim.x) {
            int ch = (int)keys_in[(b * KN + k) * 2];
            atomicAdd(&cnt[ch], 1);
        }
        __syncthreads();
        if (tid == 0) {
            int acc = 0;
            for (int c = 0; c < CC; c++) {
                g_seg[b][c] = acc;
                cur[c] = acc;
                acc += cnt[c];
            }
            g_seg[b][CC] = acc;
        }
        __syncthreads();
        for (int k = tid; k < KN; k += blockDim.x) {
            int   ch  = (int)keys_in[(b * KN + k) * 2];
            float pos = keys_in[(b * KN + k) * 2 + 1];
            int r = atomicAdd(&cur[ch], 1);
            g_pos[b][r] = pos;
            g_val[b][r] = values[(b * KN + k) * CC + ch];
        }
    }
}

// ============================================================
// Kernel 2: main pairwise accumulation via table lookup.
// grid = (Q/128, 16/CHB, B), block = 128, thread = one query.
// Inner loop is branch-free: clamped table read + SEL mask.
// ============================================================
__global__ void main_kernel(const float* __restrict__ queries,
                            const float* __restrict__ Wd,
                            const float* __restrict__ bd) {
    extern __shared__ float2 sm[];
    float2* stab = sm;                 // CHB * NTAB pairs (t[i], t[i+1])
    float2* skey = sm + CHB * NTAB;    // (pos, val) for this channel chunk

    int tid = threadIdx.x;
    int b   = blockIdx.z;
    int c0  = blockIdx.y * CHB;
    int q0  = blockIdx.x * QTHREADS;

    int soff[CHB + 1];
#pragma unroll
    for (int i = 0; i <= CHB; i++) soff[i] = g_seg[b][c0 + i];
    int s0  = soff[0];
    int len = soff[CHB] - s0;

    // stage table chunk: pairs from scalar table (coalesced reads)
#pragma unroll
    for (int cl = 0; cl < CHB; cl++) {
        const float* t1 = g_tab1 + (c0 + cl) * (NTAB + 1);
        for (int i = tid; i < NTAB; i += QTHREADS)
            stab[cl * NTAB + i] = make_float2(t1[i], t1[i + 1]);
    }
    // stage keys of this chunk
    for (int k = tid; k < len; k += QTHREADS)
        skey[k] = make_float2(g_pos[b][s0 + k], g_val[b][s0 + k]);
    __syncthreads();

    float qv  = queries[b * QQ + q0 + tid];
    float wdv = Wd[0];
    float bdv = bd[0];
    const float SCALE = (float)NTAB / WINDOW;
    int qi = (b * QQ + q0 + tid) * (2 * CC);

#pragma unroll
    for (int cl = 0; cl < CHB; cl++) {
        int kb = soff[cl] - s0;
        int ke = soff[cl + 1] - s0;
        const float2* tb = stab + cl * NTAB;
        float den = 0.0f, num = 0.0f;
#pragma unroll 4
        for (int k = kb; k < ke; k++) {
            float2 kv = skey[k];                 // warp-uniform broadcast LDS
            float ad = fabsf(kv.x - qv);         // identical to ref's |pos - q|
            float t  = ad * SCALE;
            int   i  = (int)t;
            i = i < (NTAB - 1) ? i : (NTAB - 1); // clamp (also edge-safe)
            float fr = t - (float)i;
            float2 tt = tb[i];                   // unconditional LDS.64
            float w = fmaf(tt.y - tt.x, fr, tt.x);
            w = (ad < WINDOW) ? w : 0.0f;        // SEL, no branch
            den += w;
            num = fmaf(w, kv.y, num);
        }
        float target = num / (den + 1e-5f);
        float x  = (den * 0.1f - 1.0f) * wdv + bdv;
        float dn = 1.0f / (1.0f + expf(-x));
        g_td[qi + c0 + cl]      = target;
        g_td[qi + CC + c0 + cl] = dn;
    }
}

// ============================================================
// Kernel 3: epilogue  out = [targets | dens] @ Wr^T + br
// block = 256 threads = 8 queries x 32 outputs; grid = B*Q/8
// ============================================================
__global__ void epilogue_kernel(const float* __restrict__ Wr,
                                const float* __restrict__ br,
                                float* __restrict__ out) {
    __shared__ float sWrT[2 * CC][OUTD];   // transposed: sWrT[i][o] = Wr[o][i]
    __shared__ float sbr[OUTD];
    __shared__ float scat[8][2 * CC];
    int tid = threadIdx.x;

    // stage ALL of Wr transposed: 1024 elements, 256 threads -> 4 each
#pragma unroll
    for (int e = tid; e < OUTD * 2 * CC; e += 256) {
        int o = e / (2 * CC);
        int i = e % (2 * CC);
        sWrT[i][o] = Wr[e];
    }
    if (tid < OUTD) sbr[tid] = br[tid];

    int q0 = blockIdx.x * 8;               // flat (b,q) base
    scat[tid >> 5][tid & 31] = g_td[q0 * (2 * CC) + tid];
    __syncthreads();

    int ql = tid >> 5;                     // warp = one query
    int o  = tid & 31;                     // lane = one output
    float acc = sbr[o];
#pragma unroll
    for (int i = 0; i < 2 * CC; i++)
        acc = fmaf(sWrT[i][o], scat[ql][i], acc);   // conflict-free + broadcast
    out[(q0 + ql) * OUTD + o] = acc;
}

// ============================================================
extern "C" void kernel_launch(void* const* d_in, const int* in_sizes, int n_in,
                              void* d_out, int out_size) {
    const float* keys_in = (const float*)d_in[0];
    const float* queries = (const float*)d_in[1];
    const float* values  = (const float*)d_in[2];
    const float* W0 = (const float*)d_in[3];
    const float* b0 = (const float*)d_in[4];
    const float* W1 = (const float*)d_in[5];
    const float* b1 = (const float*)d_in[6];
    const float* W2 = (const float*)d_in[7];
    const float* b2 = (const float*)d_in[8];
    const float* W3 = (const float*)d_in[9];
    const float* b3 = (const float*)d_in[10];
    const float* Wd = (const float*)d_in[11];
    const float* bd = (const float*)d_in[12];
    const float* Wr = (const float*)d_in[13];
    const float* br = (const float*)d_in[14];
    float* out = (float*)d_out;

    const size_t main_smem = (size_t)(CHB * NTAB) * sizeof(float2)
                           + (size_t)KN * sizeof(float2);
    cudaFuncSetAttribute(main_kernel, cudaFuncAttributeMaxDynamicSharedMemorySize,
                         (int)main_smem);

    prep_kernel<<<CC * TBPC + BB, 256>>>(keys_in, values,
                                         W0, b0, W1, b1, W2, b2, W3, b3);

    dim3 mgrid(QQ / QTHREADS, CC / CHB, BB);
    main_kernel<<<mgrid, QTHREADS, main_smem>>>(queries, Wd, bd);

    epilogue_kernel<<<BB * QQ / 8, 256>>>(Wr, br, out);
}